// round 9
// baseline (speedup 1.0000x reference)
#include <cuda_runtime.h>
#include <cstdint>

// Problem constants
#define B_TOTAL 4096
#define T_STEPS 1024
#define HID     64
#define GATES3  192              // 3*HID
#define NB      4                // batch elements per warp (warp-private)
#define WARPS   8                // 8 warps -> 2 per SMSP
#define THREADS (WARPS * 32)     // 256
#define BPC     (WARPS * NB)     // 32 batches per CTA
#define CTAS    (B_TOTAL / BPC)  // 128
#define QREG    5                // k-quads cached in registers (k < 20)

// packed fp32x2 FMA (Blackwell FFMA2 — 2 MACs per lane-op)
__device__ __forceinline__ unsigned long long ffma2(unsigned long long a,
                                                    unsigned long long b,
                                                    unsigned long long c) {
    unsigned long long d;
    asm("fma.rn.f32x2 %0, %1, %2, %3;" : "=l"(d) : "l"(a), "l"(b), "l"(c));
    return d;
}
__device__ __forceinline__ float lo32(unsigned long long v) {
    return __uint_as_float((unsigned)v);
}
__device__ __forceinline__ float hi32(unsigned long long v) {
    return __uint_as_float((unsigned)(v >> 32));
}
__device__ __forceinline__ unsigned long long pack2(float lo, float hi) {
    return ((unsigned long long)__float_as_uint(hi) << 32) | __float_as_uint(lo);
}

// Hardware tanh (single MUFU op)
__device__ __forceinline__ float tanh_hw(float v) {
    float r;
    asm("tanh.approx.f32 %0, %1;" : "=f"(r) : "f"(v));
    return r;
}
// sigmoid(v) = 0.5*tanh(v/2) + 0.5
__device__ __forceinline__ float sigm(float v) {
    return fmaf(0.5f, tanh_hw(0.5f * v), 0.5f);
}
__device__ __forceinline__ float lrelu(float v) {
    return v > 0.0f ? v : 0.01f * v;
}

__global__ __launch_bounds__(THREADS, 1)
void gru_fused(const float* __restrict__ x,
               const float* __restrict__ wih_g, const float* __restrict__ whh_g,
               const float* __restrict__ bih_g, const float* __restrict__ bhh_g,
               const float* __restrict__ w1, const float* __restrict__ b1,
               const float* __restrict__ w2, const float* __restrict__ b2,
               const float* __restrict__ w3, const float* __restrict__ b3,
               float* __restrict__ out)
{
    extern __shared__ float smem[];
    // Wq layout: [16 k-quads][192 rows] of float4: Wq[q][row] = W[row][4q..4q+3]
    // Lanes index by row (consecutive) at warp-uniform q:
    //   weight LDS.128 conflict-free; h LDS.128 warp-uniform -> broadcast.
    float* wq  = smem;                            // 16*192*4 floats = 48KB
    float* h_s = smem + 16 * GATES3 * 4;          // [WARPS][2][NB][HID] = 16KB

    const int tid = threadIdx.x;
    const int w   = tid >> 5;
    const int l   = tid & 31;

    // Stage W_hh transposed into smem (float4 units: global i = row*16 + q)
    {
        const float4* whh4 = (const float4*)whh_g;
        float4* wq4 = (float4*)wq;
        for (int i = tid; i < GATES3 * 16; i += THREADS) {
            const int row = i >> 4;
            const int q = i & 15;
            wq4[q * GATES3 + row] = whh4[i];
        }
    }

    // Zero both h buffers for this warp (h0 = 0). Warp-private: no CTA coupling.
    float* hw = h_s + w * (2 * NB * HID);
    for (int i = l; i < 2 * NB * HID; i += 32) hw[i] = 0.0f;

    __syncthreads();   // only for the shared weight staging

    const int b0 = (blockIdx.x * WARPS + w) * NB;

    // Per-lane resident params. j = gate*2 + p  ->  row = gate*64 + l + 32*p
    float wih[6], bih[6], bhh[6];
    int wrow[6];
#pragma unroll
    for (int g = 0; g < 3; ++g) {
#pragma unroll
        for (int p = 0; p < 2; ++p) {
            const int j = g * 2 + p;
            const int row = g * HID + l + 32 * p;
            wrow[j] = row * 4;           // float offset into a Wq[q] slab
            wih[j] = __ldg(&wih_g[row]);
            bih[j] = __ldg(&bih_g[row]);
            bhh[j] = __ldg(&bhh_g[row]);
        }
    }

    // Register-cache the first QREG k-quads of this lane's 6 weight rows.
    ulonglong2 wreg[6][QREG];
#pragma unroll
    for (int j = 0; j < 6; ++j)
#pragma unroll
        for (int qq = 0; qq < QREG; ++qq)
            wreg[j][qq] = *(const ulonglong2*)(wq + qq * (GATES3 * 4) + wrow[j]);

    const float* xrow[NB];
#pragma unroll
    for (int b = 0; b < NB; ++b) xrow[b] = x + (size_t)(b0 + b) * T_STEPS;

    float hreg0[NB], hreg1[NB];      // this lane's own h values (indices l, l+32)
    float xcur[NB], xnxt[NB];
#pragma unroll
    for (int b = 0; b < NB; ++b) {
        hreg0[b] = 0.0f;
        hreg1[b] = 0.0f;
        xcur[b] = __ldg(&xrow[b][0]);
    }

    // ---------------- recurrence (warp-private, no CTA barriers) ----------------
    for (int t = 0; t < T_STEPS; ++t) {
        const float* hc = hw + (t & 1) * (NB * HID);
        float*       hn = hw + ((t + 1) & 1) * (NB * HID);

        // Prefetch x for next step (latency hidden across the whole step)
        const int tn = (t + 1) & (T_STEPS - 1);
#pragma unroll
        for (int b = 0; b < NB; ++b) xnxt[b] = __ldg(&xrow[b][tn]);

        // Packed accumulators: lo = even-k partial (+ b_hh), hi = odd-k partial
        unsigned long long acc[NB][6];
#pragma unroll
        for (int b = 0; b < NB; ++b)
#pragma unroll
            for (int j = 0; j < 6; ++j) acc[b][j] = pack2(bhh[j], 0.0f);

        // Fully unrolled q-loop; 6 FFMA2 per hv load -> good issue economics.
#pragma unroll
        for (int q = 0; q < 16; ++q) {
            // h quad per batch: warp-uniform address -> broadcast (1 wavefront)
            ulonglong2 hv[NB];
#pragma unroll
            for (int b = 0; b < NB; ++b)
                hv[b] = *(const ulonglong2*)(hc + b * HID + q * 4);

            ulonglong2 wv[6];
            if (q < QREG) {
#pragma unroll
                for (int j = 0; j < 6; ++j) wv[j] = wreg[j][q];
            } else {
                const float* wqq = wq + q * (GATES3 * 4);
#pragma unroll
                for (int j = 0; j < 6; ++j)
                    wv[j] = *(const ulonglong2*)(wqq + wrow[j]);
            }

#pragma unroll
            for (int j = 0; j < 6; ++j) {
#pragma unroll
                for (int b = 0; b < NB; ++b) {
                    acc[b][j] = ffma2(wv[j].x, hv[b].x, acc[b][j]);
                    acc[b][j] = ffma2(wv[j].y, hv[b].y, acc[b][j]);
                }
            }
        }

        // Gates + state update (lane owns h indices l and l+32 per batch)
#pragma unroll
        for (int b = 0; b < NB; ++b) {
            const float xt = xcur[b];
            float gh[6];
#pragma unroll
            for (int j = 0; j < 6; ++j) gh[j] = lo32(acc[b][j]) + hi32(acc[b][j]);

            const float r0v = sigm(fmaf(wih[0], xt, bih[0]) + gh[0]);
            const float r1v = sigm(fmaf(wih[1], xt, bih[1]) + gh[1]);
            const float z0v = sigm(fmaf(wih[2], xt, bih[2]) + gh[2]);
            const float z1v = sigm(fmaf(wih[3], xt, bih[3]) + gh[3]);
            const float n0v = tanh_hw(fmaf(wih[4], xt, bih[4]) + r0v * gh[4]);
            const float n1v = tanh_hw(fmaf(wih[5], xt, bih[5]) + r1v * gh[5]);

            const float h0 = n0v + z0v * (hreg0[b] - n0v);
            const float h1 = n1v + z1v * (hreg1[b] - n1v);
            hreg0[b] = h0;
            hreg1[b] = h1;
            hn[b * HID + l]      = h0;
            hn[b * HID + l + 32] = h1;
            xcur[b] = xnxt[b];
        }
        __syncwarp();   // order this step's STS before next step's LDS (warp-local)
    }

    // ---------------- MLP head: 64 -> 32 -> 16 -> 1 ----------------
    // T even => final h is in buffer 0; buffer 1 is free scratch.
    const float* hf  = hw;                 // [NB][HID]
    float*       scr = hw + NB * HID;      // 32 floats scratch

#pragma unroll
    for (int b = 0; b < NB; ++b) {
        const float* hb = hf + b * HID;

        // layer 1: each lane computes one of 32 outputs
        float a1 = __ldg(&b1[l]);
#pragma unroll 8
        for (int k = 0; k < HID; ++k)
            a1 = fmaf(__ldg(&w1[l * HID + k]), hb[k], a1);
        scr[l] = lrelu(a1);
        __syncwarp();

        // layer 2 (lanes 0..15) + layer 3 partials
        float part = 0.0f;
        if (l < 16) {
            float a2 = __ldg(&b2[l]);
#pragma unroll
            for (int k = 0; k < 32; ++k)
                a2 = fmaf(__ldg(&w2[l * 32 + k]), scr[k], a2);
            part = __ldg(&w3[l]) * lrelu(a2);
        }
#pragma unroll
        for (int off = 8; off; off >>= 1)
            part += __shfl_down_sync(0xffffffffu, part, off);
        if (l == 0) out[b0 + b] = part + __ldg(&b3[0]);
        __syncwarp();
    }
}

extern "C" void kernel_launch(void* const* d_in, const int* in_sizes, int n_in,
                              void* d_out, int out_size)
{
    const float* x     = (const float*)d_in[0];
    const float* wih   = (const float*)d_in[1];
    const float* whh   = (const float*)d_in[2];
    const float* bih   = (const float*)d_in[3];
    const float* bhh   = (const float*)d_in[4];
    const float* w1    = (const float*)d_in[5];
    const float* b1    = (const float*)d_in[6];
    const float* w2    = (const float*)d_in[7];
    const float* b2    = (const float*)d_in[8];
    const float* w3    = (const float*)d_in[9];
    const float* b3    = (const float*)d_in[10];
    float* out = (float*)d_out;

    const int smem_bytes = (16 * GATES3 * 4 + WARPS * 2 * NB * HID) * (int)sizeof(float); // 64KB
    cudaFuncSetAttribute(gru_fused, cudaFuncAttributeMaxDynamicSharedMemorySize, smem_bytes);

    gru_fused<<<CTAS, THREADS, smem_bytes>>>(x, wih, whh, bih, bhh,
                                             w1, b1, w2, b2, w3, b3, out);
}

// round 10
// speedup vs baseline: 1.1936x; 1.1936x over previous
#include <cuda_runtime.h>
#include <cstdint>

// Problem constants
#define B_TOTAL 4096
#define T_STEPS 1024
#define HID     64
#define GATES3  192              // 3*HID
#define NB      7                // batch elements per PAIR of warps
#define PAIRS   4                // pairs per CTA
#define WARPS   (PAIRS * 2)      // 8 warps -> 2 per SMSP
#define THREADS (WARPS * 32)     // 256
#define BPC     (PAIRS * NB)     // 28 batches per CTA
#define CTAS    ((B_TOTAL + BPC - 1) / BPC)   // 147
#define QREG    6                // k-quads cached in registers (k < 24)

// packed fp32x2 FMA (Blackwell FFMA2 — 2 MACs per lane-op)
__device__ __forceinline__ unsigned long long ffma2(unsigned long long a,
                                                    unsigned long long b,
                                                    unsigned long long c) {
    unsigned long long d;
    asm("fma.rn.f32x2 %0, %1, %2, %3;" : "=l"(d) : "l"(a), "l"(b), "l"(c));
    return d;
}
__device__ __forceinline__ float lo32(unsigned long long v) {
    return __uint_as_float((unsigned)v);
}
__device__ __forceinline__ float hi32(unsigned long long v) {
    return __uint_as_float((unsigned)(v >> 32));
}
__device__ __forceinline__ unsigned long long pack2(float lo, float hi) {
    return ((unsigned long long)__float_as_uint(hi) << 32) | __float_as_uint(lo);
}

// Hardware tanh (single MUFU op)
__device__ __forceinline__ float tanh_hw(float v) {
    float r;
    asm("tanh.approx.f32 %0, %1;" : "=f"(r) : "f"(v));
    return r;
}
// sigmoid(v) = 0.5*tanh(v/2) + 0.5  -> 1 MUFU + 2 FMA, no dependent rcp chain
__device__ __forceinline__ float sigm(float v) {
    return fmaf(0.5f, tanh_hw(0.5f * v), 0.5f);
}
__device__ __forceinline__ float lrelu(float v) {
    return v > 0.0f ? v : 0.01f * v;
}

__global__ __launch_bounds__(THREADS, 1)
void gru_fused(const float* __restrict__ x,
               const float* __restrict__ wih_g, const float* __restrict__ whh_g,
               const float* __restrict__ bih_g, const float* __restrict__ bhh_g,
               const float* __restrict__ w1, const float* __restrict__ b1,
               const float* __restrict__ w2, const float* __restrict__ b2,
               const float* __restrict__ w3, const float* __restrict__ b3,
               float* __restrict__ out)
{
    extern __shared__ float smem[];
    // Wq layout: [16 k-quads][192 rows] of float4: Wq[q][row] = W[row][4q..4q+3]
    // Lanes index by row (consecutive) at warp-uniform q:
    //   weight LDS.128 conflict-free; h LDS.128 warp-uniform -> broadcast.
    float* wq  = smem;                            // 16*192*4 floats = 48KB
    float* h_s = smem + 16 * GATES3 * 4;          // [PAIRS][2][NB][HID]

    const int tid  = threadIdx.x;
    const int w    = tid >> 5;
    const int l    = tid & 31;
    // Pair partners on ADJACENT SMSPs; each SMSP hosts warps from two
    // INDEPENDENT pairs so barrier phases drift and one pair's gate tail
    // overlaps the other's FFMA stream.
    const int pair = w >> 1;       // 0..3
    const int half = w & 1;        // 0: h[0:32), 1: h[32:64)

    // Stage W_hh transposed into smem (float4 units: global i = row*16 + q)
    {
        const float4* whh4 = (const float4*)whh_g;
        float4* wq4 = (float4*)wq;
        for (int i = tid; i < GATES3 * 16; i += THREADS) {
            const int row = i >> 4;
            const int q = i & 15;
            wq4[q * GATES3 + row] = whh4[i];
        }
    }

    // Zero both h buffers for this pair (h0 = 0)
    float* hp = h_s + pair * (2 * NB * HID);
    for (int i = half * 32 + l; i < 2 * NB * HID; i += 64) hp[i] = 0.0f;

    __syncthreads();

    const int b0 = blockIdx.x * BPC + pair * NB;
    const int hidx = l + 32 * half;   // the h index this lane owns
    const int barid = pair + 1;       // named barrier per pair (64 threads)

    // Per-lane resident params: one row per gate g -> row = g*64 + hidx
    float wih[3], bih[3], bhh[3];
    int wrow[3];
#pragma unroll
    for (int g = 0; g < 3; ++g) {
        const int row = g * HID + hidx;
        wrow[g] = row * 4;            // float offset into a Wq[q] slab
        wih[g] = __ldg(&wih_g[row]);
        bih[g] = __ldg(&bih_g[row]);
        bhh[g] = __ldg(&bhh_g[row]);
    }

    // Register-cache the first QREG k-quads of this lane's 3 weight rows.
    ulonglong2 wreg[3][QREG];
#pragma unroll
    for (int g = 0; g < 3; ++g)
#pragma unroll
        for (int qq = 0; qq < QREG; ++qq)
            wreg[g][qq] = *(const ulonglong2*)(wq + qq * (GATES3 * 4) + wrow[g]);

    const float* xrow[NB];
#pragma unroll
    for (int b = 0; b < NB; ++b) {
        int bb = b0 + b;
        if (bb >= B_TOTAL) bb = B_TOTAL - 1;   // tail CTA: clamp (results discarded)
        xrow[b] = x + (size_t)bb * T_STEPS;
    }

    float hreg[NB];                   // this lane's own h values
    float xcur[NB], xnxt[NB];
#pragma unroll
    for (int b = 0; b < NB; ++b) {
        hreg[b] = 0.0f;
        xcur[b] = __ldg(&xrow[b][0]);
    }

    // ---------------- recurrence ----------------
    for (int t = 0; t < T_STEPS; ++t) {
        const float* hc = hp + (t & 1) * (NB * HID);
        float*       hn = hp + ((t + 1) & 1) * (NB * HID);

        // Prefetch x for next step (consumed ~1 full step later -> latency hidden)
        const int tn = (t + 1) & (T_STEPS - 1);
#pragma unroll
        for (int b = 0; b < NB; ++b) xnxt[b] = __ldg(&xrow[b][tn]);

        // Packed accumulators: lo = even-k partial (+ b_hh), hi = odd-k partial
        unsigned long long acc[NB][3];
#pragma unroll
        for (int b = 0; b < NB; ++b)
#pragma unroll
            for (int g = 0; g < 3; ++g) acc[b][g] = pack2(bhh[g], 0.0f);

        // Fully unrolled q-loop; straightline code lets ptxas hoist LDS far ahead.
#pragma unroll
        for (int q = 0; q < 16; ++q) {
            // h quad per batch: warp-uniform address -> broadcast (1 wavefront)
            ulonglong2 hv[NB];
#pragma unroll
            for (int b = 0; b < NB; ++b)
                hv[b] = *(const ulonglong2*)(hc + b * HID + q * 4);

            ulonglong2 wv[3];
            if (q < QREG) {
#pragma unroll
                for (int g = 0; g < 3; ++g) wv[g] = wreg[g][q];
            } else {
                const float* wqq = wq + q * (GATES3 * 4);
#pragma unroll
                for (int g = 0; g < 3; ++g)
                    wv[g] = *(const ulonglong2*)(wqq + wrow[g]);
            }

#pragma unroll
            for (int g = 0; g < 3; ++g) {
#pragma unroll
                for (int b = 0; b < NB; ++b) {
                    acc[b][g] = ffma2(wv[g].x, hv[b].x, acc[b][g]);
                    acc[b][g] = ffma2(wv[g].y, hv[b].y, acc[b][g]);
                }
            }
        }

        // Gates + state update (lane owns h index hidx for each batch).
        // HW tanh: 3 MUFU per batch, no dependent rcp chains.
#pragma unroll
        for (int b = 0; b < NB; ++b) {
            const float xt = xcur[b];
            const float ghr = lo32(acc[b][0]) + hi32(acc[b][0]);
            const float ghz = lo32(acc[b][1]) + hi32(acc[b][1]);
            const float ghn = lo32(acc[b][2]) + hi32(acc[b][2]);

            const float rv = sigm(fmaf(wih[0], xt, bih[0]) + ghr);
            const float zv = sigm(fmaf(wih[1], xt, bih[1]) + ghz);
            const float nv = tanh_hw(fmaf(wih[2], xt, bih[2]) + rv * ghn);

            const float hnew = nv + zv * (hreg[b] - nv);
            hreg[b] = hnew;
            hn[b * HID + hidx] = hnew;
            xcur[b] = xnxt[b];
        }
        // Pair-local barrier (2 warps, 64 threads): publishes h halves, drains STS
        asm volatile("bar.sync %0, %1;" :: "r"(barid), "r"(64) : "memory");
    }

    // ---------------- MLP head: 64 -> 32 -> 16 -> 1 ----------------
    // T even => final h is in buffer 0; buffer 1 is free scratch.
    const float* hf  = hp;                          // [NB][HID]
    float*       scr = hp + NB * HID + half * 32;   // 32 floats per warp

    // Each warp of the pair handles alternating batches.
#pragma unroll
    for (int b = 0; b < NB; ++b) {
        if ((b & 1) != half) continue;
        const float* hb = hf + b * HID;

        // layer 1: each lane computes one of 32 outputs
        float a1 = __ldg(&b1[l]);
#pragma unroll 8
        for (int k = 0; k < HID; ++k)
            a1 = fmaf(__ldg(&w1[l * HID + k]), hb[k], a1);
        scr[l] = lrelu(a1);
        __syncwarp();

        // layer 2 (lanes 0..15) + layer 3 partials
        float part = 0.0f;
        if (l < 16) {
            float a2 = __ldg(&b2[l]);
#pragma unroll
            for (int k = 0; k < 32; ++k)
                a2 = fmaf(__ldg(&w2[l * 32 + k]), scr[k], a2);
            part = __ldg(&w3[l]) * lrelu(a2);
        }
#pragma unroll
        for (int off = 8; off; off >>= 1)
            part += __shfl_down_sync(0xffffffffu, part, off);
        if (l == 0 && b0 + b < B_TOTAL) out[b0 + b] = part + __ldg(&b3[0]);
        __syncwarp();
    }
}

extern "C" void kernel_launch(void* const* d_in, const int* in_sizes, int n_in,
                              void* d_out, int out_size)
{
    const float* x     = (const float*)d_in[0];
    const float* wih   = (const float*)d_in[1];
    const float* whh   = (const float*)d_in[2];
    const float* bih   = (const float*)d_in[3];
    const float* bhh   = (const float*)d_in[4];
    const float* w1    = (const float*)d_in[5];
    const float* b1    = (const float*)d_in[6];
    const float* w2    = (const float*)d_in[7];
    const float* b2    = (const float*)d_in[8];
    const float* w3    = (const float*)d_in[9];
    const float* b3    = (const float*)d_in[10];
    float* out = (float*)d_out;

    const int smem_bytes = (16 * GATES3 * 4 + PAIRS * 2 * NB * HID) * (int)sizeof(float);
    cudaFuncSetAttribute(gru_fused, cudaFuncAttributeMaxDynamicSharedMemorySize, smem_bytes);

    gru_fused<<<CTAS, THREADS, smem_bytes>>>(x, wih, whh, bih, bhh,
                                             w1, b1, w2, b2, w3, b3, out);
}